// round 1
// baseline (speedup 1.0000x reference)
#include <cuda_runtime.h>
#include <math.h>

#define BTOT 4
#define CINV 128
#define HHV 64
#define WWV 64
#define PLV 256
#define ATTV 64
#define RRV 16
#define STEPSV 6
#define EPSV 1e-6f
#define MTOT (BTOT*HHV*WWV)   /* 16384 */
#define HWV (HHV*WWV)         /* 4096 */

// ---------------- scratch (device globals; no runtime allocation) ----------------
__device__ float g_y[MTOT*PLV];      // conv1 output, NHWC [pix][p]
__device__ float g_xm[MTOT*PLV];     // depthwise+bias output, NHWC
__device__ float g_xl[MTOT*PLV];     // relu(lower) output
__device__ float g_feat[MTOT*PLV];   // relu(xm+xr)
__device__ float g_w1t[CINV*PLV];    // conv1_w transposed [c][p]
__device__ float g_lwt[PLV*PLV];     // lower_w transposed [k][n]
__device__ float g_fwt[PLV*CINV];    // fc_w transposed [p][o]
__device__ float g_att[BTOT*PLV];
__device__ float g_pool_sum[BTOT*PLV];
__device__ int   g_pool_max[BTOT*PLV];

// ---------------- init: zero pools + transpose weights ----------------
__global__ void init_kernel(const float* __restrict__ w1,
                            const float* __restrict__ lw,
                            const float* __restrict__ fw)
{
    int i = blockIdx.x * 256 + threadIdx.x;     // grid 256 -> 65536 threads
    if (i < BTOT*PLV) { g_pool_sum[i] = 0.f; g_pool_max[i] = 0; }
    if (i < CINV*PLV) { int c = i / PLV, p = i % PLV; g_w1t[i] = w1[p*CINV + c]; }
    if (i < PLV*PLV)  { int k = i / PLV, n = i % PLV; g_lwt[i] = lw[n*PLV + k]; }
    if (i < PLV*CINV) { int p = i / CINV, o = i % CINV; g_fwt[i] = fw[o*PLV + p]; }
}

// ---------------- tiled SIMT GEMM (128x128 tile, 8x8 per thread) ----------------
// MODE 0: y = x @ w1t            (A = x, k-major layout; C = g_y)
// MODE 1: xl = relu(xm@lwt + b)  (A = g_xm row-major; C = g_xl)
// MODE 2: out = (feat*att)@fwt+b (A = g_feat row-major scaled by g_att; C = param, NCHW)
template<int KDIM, int MODE, int ALAYOUT>
__global__ __launch_bounds__(256)
void gemm_kernel(const float* __restrict__ Aparam, const float* __restrict__ bias,
                 float* __restrict__ Cparam, int Ncols)
{
    const float* A  = (MODE==0) ? Aparam : (MODE==1) ? g_xm : g_feat;
    const float* Bt = (MODE==0) ? g_w1t  : (MODE==1) ? g_lwt : g_fwt;
    float*       C  = (MODE==0) ? g_y    : (MODE==1) ? g_xl  : Cparam;

    __shared__ float As[8][132];
    __shared__ float Bs[8][132];
    const int m0 = blockIdx.x * 128;
    const int n0 = blockIdx.y * 128;
    const int t  = threadIdx.x;
    const int tx = t & 15;
    const int ty = t >> 4;
    const int batch = m0 >> 12;

    float acc[8][8];
#pragma unroll
    for (int i = 0; i < 8; i++)
#pragma unroll
        for (int j = 0; j < 8; j++) acc[i][j] = 0.f;

    for (int k0 = 0; k0 < KDIM; k0 += 8) {
        if (ALAYOUT == 0) {
            const int ka = t >> 5, ma = (t & 31) << 2;
            const float4 v = *(const float4*)(A + (size_t)batch*KDIM*HWV
                                              + (size_t)(k0+ka)*HWV + (m0 & (HWV-1)) + ma);
            *(float4*)&As[ka][ma] = v;
        } else {
            const int ma = t >> 1, kv = (t & 1) << 2;
            float4 v = *(const float4*)(A + (size_t)(m0+ma)*KDIM + k0 + kv);
            if (MODE == 2) {
                const float4 sc = *(const float4*)(g_att + batch*PLV + k0 + kv);
                v.x *= sc.x; v.y *= sc.y; v.z *= sc.z; v.w *= sc.w;
            }
            As[kv+0][ma] = v.x; As[kv+1][ma] = v.y;
            As[kv+2][ma] = v.z; As[kv+3][ma] = v.w;
        }
        {
            const int kb = t >> 5, nb = (t & 31) << 2;
            *(float4*)&Bs[kb][nb] = *(const float4*)(Bt + (size_t)(k0+kb)*Ncols + n0 + nb);
        }
        __syncthreads();
#pragma unroll
        for (int k = 0; k < 8; k++) {
            float4 a0 = *(float4*)&As[k][ty<<2];
            float4 a1 = *(float4*)&As[k][64 + (ty<<2)];
            float4 b0 = *(float4*)&Bs[k][tx<<2];
            float4 b1 = *(float4*)&Bs[k][64 + (tx<<2)];
            float am[8] = {a0.x,a0.y,a0.z,a0.w,a1.x,a1.y,a1.z,a1.w};
            float bn[8] = {b0.x,b0.y,b0.z,b0.w,b1.x,b1.y,b1.z,b1.w};
#pragma unroll
            for (int i = 0; i < 8; i++)
#pragma unroll
                for (int j = 0; j < 8; j++)
                    acc[i][j] = fmaf(am[i], bn[j], acc[i][j]);
        }
        __syncthreads();
    }

#pragma unroll
    for (int i = 0; i < 8; i++) {
        const int mr = (i < 4) ? ((ty<<2) + i) : (64 + (ty<<2) + i - 4);
        const int m  = m0 + mr;
#pragma unroll
        for (int jj = 0; jj < 2; jj++) {
            float4 v;
            v.x = acc[i][jj*4+0]; v.y = acc[i][jj*4+1];
            v.z = acc[i][jj*4+2]; v.w = acc[i][jj*4+3];
            const int n = n0 + (tx<<2) + jj*64;
            if (MODE == 0) {
                *(float4*)&C[(size_t)m*Ncols + n] = v;
            } else if (MODE == 1) {
                const float4 bb = *(const float4*)(bias + n);
                v.x = fmaxf(v.x + bb.x, 0.f);
                v.y = fmaxf(v.y + bb.y, 0.f);
                v.z = fmaxf(v.z + bb.z, 0.f);
                v.w = fmaxf(v.w + bb.w, 0.f);
                *(float4*)&C[(size_t)m*Ncols + n] = v;
            } else {
                const int pix = m & (HWV-1);
#pragma unroll
                for (int qq = 0; qq < 4; qq++) {
                    C[(size_t)(batch*CINV + n + qq)*HWV + pix] = acc[i][jj*4+qq] + bias[n+qq];
                }
            }
        }
    }
}

// ---------------- depthwise 3x3 + bias, NHWC ----------------
__global__ __launch_bounds__(256)
void dw_kernel(const float* __restrict__ w3, const float* __restrict__ b3)
{
    const int p = threadIdx.x;
    float wv[9];
#pragma unroll
    for (int j = 0; j < 9; j++) wv[j] = w3[p*9 + j];
    const float bb = b3[p];
    const int base = blockIdx.x * 4;
    for (int q = 0; q < 4; q++) {
        const int pix = base + q;
        const int b = pix >> 12, hw = pix & 4095, h = hw >> 6, w = hw & 63;
        float acc = bb;
#pragma unroll
        for (int ky = 0; ky < 3; ky++) {
            const int hh = h + ky - 1;
            if (hh < 0 || hh >= HHV) continue;
#pragma unroll
            for (int kx = 0; kx < 3; kx++) {
                const int ww = w + kx - 1;
                if (ww < 0 || ww >= WWV) continue;
                acc = fmaf(g_y[(size_t)((b<<12) + (hh<<6) + ww)*PLV + p], wv[ky*3+kx], acc);
            }
        }
        g_xm[(size_t)pix*PLV + p] = acc;
    }
}

// ---------------- EM iterations: one warp per pixel, coef in registers ----------------
__global__ __launch_bounds__(256, 1)
void em_kernel(const float* __restrict__ binit)
{
    __shared__ float bsum[PLV];
    __shared__ int   bmx[PLV];
    const int t = threadIdx.x;
    bsum[t] = 0.f; bmx[t] = 0;
    __syncthreads();

    const int w = t >> 5, lane = t & 31;
    const int m = blockIdx.x * 8 + w;

    // bases init (l2norm over singleton axis == elementwise v/max(|v|,1e-12))
    float b[RRV];
#pragma unroll
    for (int r = 0; r < RRV; r++) {
        const float v = binit[m*RRV + r];
        b[r] = v / fmaxf(fabsf(v), 1e-12f);
    }
    // x = xl row (this pixel), 8 values per lane (n = lane + 32*j)
    float x[8];
#pragma unroll
    for (int j = 0; j < 8; j++) x[j] = g_xl[(size_t)m*PLV + lane + 32*j];

    // coef init: softmax over r of x[n]*b[r]
    float cf[8][RRV];
#pragma unroll
    for (int j = 0; j < 8; j++) {
        const float xn = x[j];
        float tv[RRV];
        float mx = -3.4e38f;
#pragma unroll
        for (int r = 0; r < RRV; r++) { tv[r] = xn * b[r]; mx = fmaxf(mx, tv[r]); }
        float s = 0.f;
#pragma unroll
        for (int r = 0; r < RRV; r++) { const float e = __expf(tv[r] - mx); cf[j][r] = e; s += e; }
        const float inv = __fdividef(1.f, s);
#pragma unroll
        for (int r = 0; r < RRV; r++) cf[j][r] *= inv;
    }

    for (int step = 0; step < STEPSV; step++) {
        // coef update: cf *= x[n]*b[r] / (s[n]*b[r] + eps),  s[n] = cf[n,:]·b
#pragma unroll
        for (int j = 0; j < 8; j++) {
            float s = 0.f;
#pragma unroll
            for (int r = 0; r < RRV; r++) s = fmaf(cf[j][r], b[r], s);
            const float xn = x[j];
#pragma unroll
            for (int r = 0; r < RRV; r++) {
                const float num = xn * b[r];
                const float den = fmaf(s, b[r], EPSV);
                cf[j][r] = cf[j][r] * num * __fdividef(1.f, den);
            }
        }
        // bases update: num2[r]=Σ_n x[n]cf[n,r]; den2[r]=Σ_n s'[n]cf[n,r], s'=cf·b
        float p[RRV], q[RRV];
#pragma unroll
        for (int r = 0; r < RRV; r++) { p[r] = 0.f; q[r] = 0.f; }
#pragma unroll
        for (int j = 0; j < 8; j++) {
            float sp = 0.f;
#pragma unroll
            for (int r = 0; r < RRV; r++) sp = fmaf(cf[j][r], b[r], sp);
            const float xn = x[j];
#pragma unroll
            for (int r = 0; r < RRV; r++) {
                p[r] = fmaf(xn, cf[j][r], p[r]);
                q[r] = fmaf(sp, cf[j][r], q[r]);
            }
        }
#pragma unroll
        for (int off = 16; off > 0; off >>= 1) {
#pragma unroll
            for (int r = 0; r < RRV; r++) {
                p[r] += __shfl_xor_sync(0xffffffffu, p[r], off);
                q[r] += __shfl_xor_sync(0xffffffffu, q[r], off);
            }
        }
#pragma unroll
        for (int r = 0; r < RRV; r++)
            b[r] = b[r] * p[r] * __fdividef(1.f, q[r] + EPSV);
    }

    // final coef update (reference does one more after the loop, with xn == xs)
#pragma unroll
    for (int j = 0; j < 8; j++) {
        float s = 0.f;
#pragma unroll
        for (int r = 0; r < RRV; r++) s = fmaf(cf[j][r], b[r], s);
        const float xn = x[j];
#pragma unroll
        for (int r = 0; r < RRV; r++) {
            const float num = xn * b[r];
            const float den = fmaf(s, b[r], EPSV);
            cf[j][r] = cf[j][r] * num * __fdividef(1.f, den);
        }
    }

    // xr = Σ_r b[r] cf[n,r]; feat = relu(xm + xr); pooling partials
#pragma unroll
    for (int j = 0; j < 8; j++) {
        float xr = 0.f;
#pragma unroll
        for (int r = 0; r < RRV; r++) xr = fmaf(b[r], cf[j][r], xr);
        const int n = lane + 32*j;
        const float f = fmaxf(g_xm[(size_t)m*PLV + n] + xr, 0.f);
        g_feat[(size_t)m*PLV + n] = f;
        atomicAdd(&bsum[n], f);
        atomicMax(&bmx[n], __float_as_int(f));   // valid: f >= 0
    }
    __syncthreads();
    const int bb = (blockIdx.x * 8) >> 12;
    atomicAdd(&g_pool_sum[bb*PLV + t], bsum[t]);
    atomicMax(&g_pool_max[bb*PLV + t], bmx[t]);
}

// ---------------- channel attention ----------------
__global__ __launch_bounds__(256)
void ca_kernel(const float* __restrict__ ca1, const float* __restrict__ ca2,
               float* __restrict__ out)
{
    const int b = blockIdx.x;
    const int t = threadIdx.x;
    __shared__ float sAvg[PLV], sMx[PLV], h1[ATTV];
    sAvg[t] = g_pool_sum[b*PLV + t] * (1.0f/(float)HWV);
    sMx[t]  = __int_as_float(g_pool_max[b*PLV + t]);
    __syncthreads();
    if (t < ATTV) {
        float a1 = 0.f, a2 = 0.f;
        for (int p = 0; p < PLV; p++) {
            const float wv = ca1[t*PLV + p];
            a1 = fmaf(wv, sAvg[p], a1);
            a2 = fmaf(wv, sMx[p],  a2);
        }
        h1[t] = fmaxf(a1, 0.f) + fmaxf(a2, 0.f);   // second layer is linear -> sum first
    }
    __syncthreads();
    float v = 0.f;
    for (int a = 0; a < ATTV; a++) v = fmaf(h1[a], ca2[t*ATTV + a], v);
    const float att = __fdividef(1.f, 1.f + __expf(-v));
    g_att[b*PLV + t] = att;
    out[(size_t)BTOT*CINV*HWV + b*PLV + t] = att;   // att output after `out` block
}

// ---------------- launch ----------------
extern "C" void kernel_launch(void* const* d_in, const int* in_sizes, int n_in,
                              void* d_out, int out_size)
{
    const float* x       = (const float*)d_in[0];
    const float* conv1_w = (const float*)d_in[1];
    const float* conv3_w = (const float*)d_in[2];
    const float* conv3_b = (const float*)d_in[3];
    const float* lower_w = (const float*)d_in[4];
    const float* lower_b = (const float*)d_in[5];
    const float* ca1_w   = (const float*)d_in[6];
    const float* ca2_w   = (const float*)d_in[7];
    const float* fc_w    = (const float*)d_in[8];
    const float* fc_b    = (const float*)d_in[9];
    const float* bases   = (const float*)d_in[10];
    float* out = (float*)d_out;

    init_kernel<<<256, 256>>>(conv1_w, lower_w, fc_w);
    // conv1 (1x1): y[pix][p] = sum_c x[b,c,pix] * w1t[c][p]
    gemm_kernel<CINV, 0, 0><<<dim3(MTOT/128, PLV/128), 256>>>(x, nullptr, nullptr, PLV);
    // depthwise 3x3 + bias
    dw_kernel<<<MTOT/4, 256>>>(conv3_w, conv3_b);
    // xl = relu(xm @ lower_w^T + lower_b)
    gemm_kernel<PLV, 1, 1><<<dim3(MTOT/128, PLV/128), 256>>>(nullptr, lower_b, nullptr, PLV);
    // EM iterations + feat + pooling partials
    em_kernel<<<MTOT/8, 256>>>(bases);
    // channel attention (writes g_att and the att output tail)
    ca_kernel<<<BTOT, 256>>>(ca1_w, ca2_w, out);
    // out = (feat * att) @ fc_w^T + fc_b, NCHW
    gemm_kernel<PLV, 2, 1><<<dim3(MTOT/128, 1), 256>>>(nullptr, fc_b, out, CINV);
}

// round 2
// speedup vs baseline: 2.2787x; 2.2787x over previous
#include <cuda_runtime.h>
#include <math.h>

#define BTOT 4
#define CINV 128
#define HHV 64
#define WWV 64
#define PLV 256
#define ATTV 64
#define RRV 16
#define STEPSV 6
#define EPSV 1e-6f
#define MTOT (BTOT*HHV*WWV)   /* 16384 */
#define HWV (HHV*WWV)         /* 4096 */

// ---------------- scratch (device globals; no runtime allocation) ----------------
__device__ float g_y[MTOT*PLV];      // conv1 output, NHWC [pix][p]
__device__ float g_xm[MTOT*PLV];     // depthwise+bias output, NHWC
__device__ float g_xl[MTOT*PLV];     // relu(lower) output
__device__ float g_feat[MTOT*PLV];   // relu(xm+xr)
__device__ float g_w1t[CINV*PLV];    // conv1_w transposed [c][p]
__device__ float g_lwt[PLV*PLV];     // lower_w transposed [k][n]
__device__ float g_fwt[PLV*CINV];    // fc_w transposed [p][o]
__device__ float g_att[BTOT*PLV];
__device__ float g_pool_sum[BTOT*PLV];
__device__ int   g_pool_max[BTOT*PLV];

// ---------------- init: zero pools + transpose weights ----------------
__global__ void init_kernel(const float* __restrict__ w1,
                            const float* __restrict__ lw,
                            const float* __restrict__ fw)
{
    int i = blockIdx.x * 256 + threadIdx.x;     // grid 256 -> 65536 threads
    if (i < BTOT*PLV) { g_pool_sum[i] = 0.f; g_pool_max[i] = 0; }
    if (i < CINV*PLV) { int c = i / PLV, p = i % PLV; g_w1t[i] = w1[p*CINV + c]; }
    if (i < PLV*PLV)  { int k = i / PLV, n = i % PLV; g_lwt[i] = lw[n*PLV + k]; }
    if (i < PLV*CINV) { int p = i / CINV, o = i % CINV; g_fwt[i] = fw[o*PLV + p]; }
}

// ---------------- tiled SIMT GEMM (128x128 tile, 8x8 per thread, ktile 16) --------
// MODE 0: y = x @ w1t            (A = x, k-major layout; C = g_y)
// MODE 1: xl = relu(xm@lwt + b)  (A = g_xm row-major; C = g_xl)
// MODE 2: out = (feat*att)@fwt+b (A = g_feat row-major scaled by g_att; C = param, NCHW)
template<int KDIM, int MODE, int ALAYOUT>
__global__ __launch_bounds__(256, 2)
void gemm_kernel(const float* __restrict__ Aparam, const float* __restrict__ bias,
                 float* __restrict__ Cparam, int Ncols)
{
    const float* A  = (MODE==0) ? Aparam : (MODE==1) ? g_xm : g_feat;
    const float* Bt = (MODE==0) ? g_w1t  : (MODE==1) ? g_lwt : g_fwt;
    float*       C  = (MODE==0) ? g_y    : (MODE==1) ? g_xl  : Cparam;

    __shared__ float As[16][132];
    __shared__ float Bs[16][132];
    const int m0 = blockIdx.x * 128;
    const int n0 = blockIdx.y * 128;
    const int t  = threadIdx.x;
    const int tx = t & 15;
    const int ty = t >> 4;
    const int batch = m0 >> 12;

    float acc[8][8];
#pragma unroll
    for (int i = 0; i < 8; i++)
#pragma unroll
        for (int j = 0; j < 8; j++) acc[i][j] = 0.f;

    for (int k0 = 0; k0 < KDIM; k0 += 16) {
        if (ALAYOUT == 0) {
#pragma unroll
            for (int r = 0; r < 2; r++) {
                const int idx = t + 256*r;
                const int ka = idx >> 5, mv = (idx & 31) << 2;
                *(float4*)&As[ka][mv] =
                    *(const float4*)(A + (size_t)batch*KDIM*HWV
                                     + (size_t)(k0+ka)*HWV + (m0 & (HWV-1)) + mv);
            }
        } else {
#pragma unroll
            for (int r = 0; r < 2; r++) {
                const int idx = t + 256*r;
                const int ma = idx >> 2, kv = (idx & 3) << 2;
                float4 v = *(const float4*)(A + (size_t)(m0+ma)*KDIM + k0 + kv);
                if (MODE == 2) {
                    const float4 sc = *(const float4*)(g_att + batch*PLV + k0 + kv);
                    v.x *= sc.x; v.y *= sc.y; v.z *= sc.z; v.w *= sc.w;
                }
                As[kv+0][ma] = v.x; As[kv+1][ma] = v.y;
                As[kv+2][ma] = v.z; As[kv+3][ma] = v.w;
            }
        }
#pragma unroll
        for (int r = 0; r < 2; r++) {
            const int idx = t + 256*r;
            const int kb = idx >> 5, nv = (idx & 31) << 2;
            *(float4*)&Bs[kb][nv] = *(const float4*)(Bt + (size_t)(k0+kb)*Ncols + n0 + nv);
        }
        __syncthreads();
#pragma unroll
        for (int k = 0; k < 16; k++) {
            float4 a0 = *(float4*)&As[k][ty<<2];
            float4 a1 = *(float4*)&As[k][64 + (ty<<2)];
            float4 b0 = *(float4*)&Bs[k][tx<<2];
            float4 b1 = *(float4*)&Bs[k][64 + (tx<<2)];
            float am[8] = {a0.x,a0.y,a0.z,a0.w,a1.x,a1.y,a1.z,a1.w};
            float bn[8] = {b0.x,b0.y,b0.z,b0.w,b1.x,b1.y,b1.z,b1.w};
#pragma unroll
            for (int i = 0; i < 8; i++)
#pragma unroll
                for (int j = 0; j < 8; j++)
                    acc[i][j] = fmaf(am[i], bn[j], acc[i][j]);
        }
        __syncthreads();
    }

#pragma unroll
    for (int i = 0; i < 8; i++) {
        const int mr = (i < 4) ? ((ty<<2) + i) : (64 + (ty<<2) + i - 4);
        const int m  = m0 + mr;
#pragma unroll
        for (int jj = 0; jj < 2; jj++) {
            float4 v;
            v.x = acc[i][jj*4+0]; v.y = acc[i][jj*4+1];
            v.z = acc[i][jj*4+2]; v.w = acc[i][jj*4+3];
            const int n = n0 + (tx<<2) + jj*64;
            if (MODE == 0) {
                *(float4*)&C[(size_t)m*Ncols + n] = v;
            } else if (MODE == 1) {
                const float4 bb = *(const float4*)(bias + n);
                v.x = fmaxf(v.x + bb.x, 0.f);
                v.y = fmaxf(v.y + bb.y, 0.f);
                v.z = fmaxf(v.z + bb.z, 0.f);
                v.w = fmaxf(v.w + bb.w, 0.f);
                *(float4*)&C[(size_t)m*Ncols + n] = v;
            } else {
                const int pix = m & (HWV-1);
#pragma unroll
                for (int qq = 0; qq < 4; qq++) {
                    C[(size_t)(batch*CINV + n + qq)*HWV + pix] = acc[i][jj*4+qq] + bias[n+qq];
                }
            }
        }
    }
}

// ---------------- depthwise 3x3 + bias, NHWC ----------------
__global__ __launch_bounds__(256)
void dw_kernel(const float* __restrict__ w3, const float* __restrict__ b3)
{
    const int p = threadIdx.x;
    float wv[9];
#pragma unroll
    for (int j = 0; j < 9; j++) wv[j] = w3[p*9 + j];
    const float bb = b3[p];
    const int base = blockIdx.x * 4;
    for (int q = 0; q < 4; q++) {
        const int pix = base + q;
        const int b = pix >> 12, hw = pix & 4095, h = hw >> 6, w = hw & 63;
        float acc = bb;
#pragma unroll
        for (int ky = 0; ky < 3; ky++) {
            const int hh = h + ky - 1;
            if (hh < 0 || hh >= HHV) continue;
#pragma unroll
            for (int kx = 0; kx < 3; kx++) {
                const int ww = w + kx - 1;
                if (ww < 0 || ww >= WWV) continue;
                acc = fmaf(g_y[(size_t)((b<<12) + (hh<<6) + ww)*PLV + p], wv[ky*3+kx], acc);
            }
        }
        g_xm[(size_t)pix*PLV + p] = acc;
    }
}

// ---------------- FAST EM: scalar path for r-uniform bases (one warp / pixel) -----
// If all 16 initial b_r are bit-equal (true for uniform[0,1) init: v/max(v,1e-12)
// == 1.0 exactly), coef stays uniform across r by induction (all per-r arithmetic
// is identical; sums of 16 equal fp values are exact *16). The EM collapses to a
// scalar recurrence. Non-uniform warps are skipped here; em_general handles them.
__global__ __launch_bounds__(512)
void em_fast(const float* __restrict__ binit)
{
    __shared__ float bsum[PLV];
    __shared__ int   bmx[PLV];
    const int t = threadIdx.x;
    if (t < PLV) { bsum[t] = 0.f; bmx[t] = 0; }
    __syncthreads();

    const int w = t >> 5, lane = t & 31;
    const int m = blockIdx.x * 16 + w;

    float bv = 1.f;
    if (lane < RRV) {
        const float v = binit[m*RRV + lane];
        bv = v / fmaxf(fabsf(v), 1e-12f);
    }
    const float b0 = __shfl_sync(0xffffffffu, bv, 0);
    const bool uni = __all_sync(0xffffffffu, (lane >= RRV) || (bv == b0));

    if (uni) {
        float b = b0;
        float x[8], cf[8];
        {
            const float4 v0 = *(const float4*)(g_xl + (size_t)m*PLV + lane*8);
            const float4 v1 = *(const float4*)(g_xl + (size_t)m*PLV + lane*8 + 4);
            x[0]=v0.x; x[1]=v0.y; x[2]=v0.z; x[3]=v0.w;
            x[4]=v1.x; x[5]=v1.y; x[6]=v1.z; x[7]=v1.w;
        }
#pragma unroll
        for (int j = 0; j < 8; j++) cf[j] = 0.0625f;   // softmax of equal logits

#pragma unroll
        for (int step = 0; step < STEPSV; step++) {
            // coef update: den = 16*cf*b*b + eps ; cf *= (x*b)/den
            float ps = 0.f, qs = 0.f;
#pragma unroll
            for (int j = 0; j < 8; j++) {
                const float tb  = cf[j] * b;
                const float den = fmaf(16.f*tb, b, EPSV);
                const float num = x[j] * b;
                cf[j] = cf[j] * num * __fdividef(1.f, den);
                ps = fmaf(x[j],  cf[j], ps);     // p = sum x*cf
                qs = fmaf(cf[j], cf[j], qs);     // q' = sum cf^2  (q = 16*b*q')
            }
#pragma unroll
            for (int off = 16; off > 0; off >>= 1) {
                ps += __shfl_xor_sync(0xffffffffu, ps, off);
                qs += __shfl_xor_sync(0xffffffffu, qs, off);
            }
            const float den = fmaf(16.f*b, qs, EPSV);
            b = b * ps * __fdividef(1.f, den);
        }
        // final coef update
#pragma unroll
        for (int j = 0; j < 8; j++) {
            const float tb  = cf[j] * b;
            const float den = fmaf(16.f*tb, b, EPSV);
            const float num = x[j] * b;
            cf[j] = cf[j] * num * __fdividef(1.f, den);
        }
        // xr = 16*b*cf ; feat = relu(xm + xr) ; pooling
        const float4 m0v = *(const float4*)(g_xm + (size_t)m*PLV + lane*8);
        const float4 m1v = *(const float4*)(g_xm + (size_t)m*PLV + lane*8 + 4);
        const float xm8[8] = {m0v.x,m0v.y,m0v.z,m0v.w,m1v.x,m1v.y,m1v.z,m1v.w};
        float f[8];
#pragma unroll
        for (int j = 0; j < 8; j++) {
            f[j] = fmaxf(fmaf(16.f*b, cf[j], xm8[j]), 0.f);
            const int n = lane*8 + j;
            atomicAdd(&bsum[n], f[j]);
            atomicMax(&bmx[n], __float_as_int(f[j]));
        }
        float4 o0 = make_float4(f[0],f[1],f[2],f[3]);
        float4 o1 = make_float4(f[4],f[5],f[6],f[7]);
        *(float4*)(g_feat + (size_t)m*PLV + lane*8)     = o0;
        *(float4*)(g_feat + (size_t)m*PLV + lane*8 + 4) = o1;
    }
    __syncthreads();
    if (t < PLV) {
        const int bb = (blockIdx.x * 16) >> 12;
        atomicAdd(&g_pool_sum[bb*PLV + t], bsum[t]);
        atomicMax(&g_pool_max[bb*PLV + t], bmx[t]);
    }
}

// ---------------- GENERAL EM (fallback for non-uniform warps) ----------------
__global__ __launch_bounds__(256, 1)
void em_general(const float* __restrict__ binit)
{
    __shared__ float bsum[PLV];
    __shared__ int   bmx[PLV];
    const int t = threadIdx.x;
    bsum[t] = 0.f; bmx[t] = 0;
    __syncthreads();

    const int w = t >> 5, lane = t & 31;
    const int m = blockIdx.x * 8 + w;

    float b[RRV];
#pragma unroll
    for (int r = 0; r < RRV; r++) {
        const float v = binit[m*RRV + r];
        b[r] = v / fmaxf(fabsf(v), 1e-12f);
    }
    bool uni = true;
#pragma unroll
    for (int r = 1; r < RRV; r++) uni &= (b[r] == b[0]);

    bool did = false;
    if (!uni) {
        did = true;
        float x[8];
#pragma unroll
        for (int j = 0; j < 8; j++) x[j] = g_xl[(size_t)m*PLV + lane + 32*j];

        float cf[8][RRV];
#pragma unroll
        for (int j = 0; j < 8; j++) {
            const float xn = x[j];
            float tv[RRV]; float mx = -3.4e38f;
#pragma unroll
            for (int r = 0; r < RRV; r++) { tv[r] = xn * b[r]; mx = fmaxf(mx, tv[r]); }
            float s = 0.f;
#pragma unroll
            for (int r = 0; r < RRV; r++) { const float e = __expf(tv[r]-mx); cf[j][r]=e; s+=e; }
            const float inv = __fdividef(1.f, s);
#pragma unroll
            for (int r = 0; r < RRV; r++) cf[j][r] *= inv;
        }
        for (int step = 0; step < STEPSV; step++) {
#pragma unroll
            for (int j = 0; j < 8; j++) {
                float s = 0.f;
#pragma unroll
                for (int r = 0; r < RRV; r++) s = fmaf(cf[j][r], b[r], s);
                const float xn = x[j];
#pragma unroll
                for (int r = 0; r < RRV; r++) {
                    const float num = xn * b[r];
                    const float den = fmaf(s, b[r], EPSV);
                    cf[j][r] = cf[j][r] * num * __fdividef(1.f, den);
                }
            }
            float p[RRV], q[RRV];
#pragma unroll
            for (int r = 0; r < RRV; r++) { p[r]=0.f; q[r]=0.f; }
#pragma unroll
            for (int j = 0; j < 8; j++) {
                float sp = 0.f;
#pragma unroll
                for (int r = 0; r < RRV; r++) sp = fmaf(cf[j][r], b[r], sp);
                const float xn = x[j];
#pragma unroll
                for (int r = 0; r < RRV; r++) {
                    p[r] = fmaf(xn, cf[j][r], p[r]);
                    q[r] = fmaf(sp, cf[j][r], q[r]);
                }
            }
#pragma unroll
            for (int off = 16; off > 0; off >>= 1) {
#pragma unroll
                for (int r = 0; r < RRV; r++) {
                    p[r] += __shfl_xor_sync(0xffffffffu, p[r], off);
                    q[r] += __shfl_xor_sync(0xffffffffu, q[r], off);
                }
            }
#pragma unroll
            for (int r = 0; r < RRV; r++)
                b[r] = b[r] * p[r] * __fdividef(1.f, q[r] + EPSV);
        }
#pragma unroll
        for (int j = 0; j < 8; j++) {
            float s = 0.f;
#pragma unroll
            for (int r = 0; r < RRV; r++) s = fmaf(cf[j][r], b[r], s);
            const float xn = x[j];
#pragma unroll
            for (int r = 0; r < RRV; r++) {
                const float num = xn * b[r];
                const float den = fmaf(s, b[r], EPSV);
                cf[j][r] = cf[j][r] * num * __fdividef(1.f, den);
            }
        }
#pragma unroll
        for (int j = 0; j < 8; j++) {
            float xr = 0.f;
#pragma unroll
            for (int r = 0; r < RRV; r++) xr = fmaf(b[r], cf[j][r], xr);
            const int n = lane + 32*j;
            const float f = fmaxf(g_xm[(size_t)m*PLV + n] + xr, 0.f);
            g_feat[(size_t)m*PLV + n] = f;
            atomicAdd(&bsum[n], f);
            atomicMax(&bmx[n], __float_as_int(f));
        }
    }
    __syncthreads();
    if (__syncthreads_or(did)) {
        const int bb = (blockIdx.x * 8) >> 12;
        atomicAdd(&g_pool_sum[bb*PLV + t], bsum[t]);
        atomicMax(&g_pool_max[bb*PLV + t], bmx[t]);
    }
}

// ---------------- channel attention ----------------
__global__ __launch_bounds__(256)
void ca_kernel(const float* __restrict__ ca1, const float* __restrict__ ca2,
               float* __restrict__ out)
{
    const int b = blockIdx.x;
    const int t = threadIdx.x;
    __shared__ float sAvg[PLV], sMx[PLV], h1[ATTV];
    sAvg[t] = g_pool_sum[b*PLV + t] * (1.0f/(float)HWV);
    sMx[t]  = __int_as_float(g_pool_max[b*PLV + t]);
    __syncthreads();
    if (t < ATTV) {
        float a1 = 0.f, a2 = 0.f;
        for (int p = 0; p < PLV; p++) {
            const float wv = ca1[t*PLV + p];
            a1 = fmaf(wv, sAvg[p], a1);
            a2 = fmaf(wv, sMx[p],  a2);
        }
        h1[t] = fmaxf(a1, 0.f) + fmaxf(a2, 0.f);   // second layer is linear -> sum first
    }
    __syncthreads();
    float v = 0.f;
    for (int a = 0; a < ATTV; a++) v = fmaf(h1[a], ca2[t*ATTV + a], v);
    const float att = __fdividef(1.f, 1.f + __expf(-v));
    g_att[b*PLV + t] = att;
    out[(size_t)BTOT*CINV*HWV + b*PLV + t] = att;   // att output after `out` block
}

// ---------------- launch ----------------
extern "C" void kernel_launch(void* const* d_in, const int* in_sizes, int n_in,
                              void* d_out, int out_size)
{
    const float* x       = (const float*)d_in[0];
    const float* conv1_w = (const float*)d_in[1];
    const float* conv3_w = (const float*)d_in[2];
    const float* conv3_b = (const float*)d_in[3];
    const float* lower_w = (const float*)d_in[4];
    const float* lower_b = (const float*)d_in[5];
    const float* ca1_w   = (const float*)d_in[6];
    const float* ca2_w   = (const float*)d_in[7];
    const float* fc_w    = (const float*)d_in[8];
    const float* fc_b    = (const float*)d_in[9];
    const float* bases   = (const float*)d_in[10];
    float* out = (float*)d_out;

    init_kernel<<<256, 256>>>(conv1_w, lower_w, fc_w);
    gemm_kernel<CINV, 0, 0><<<dim3(MTOT/128, PLV/128), 256>>>(x, nullptr, nullptr, PLV);
    dw_kernel<<<MTOT/4, 256>>>(conv3_w, conv3_b);
    gemm_kernel<PLV, 1, 1><<<dim3(MTOT/128, PLV/128), 256>>>(nullptr, lower_b, nullptr, PLV);
    em_fast<<<MTOT/16, 512>>>(bases);
    em_general<<<MTOT/8, 256>>>(bases);
    ca_kernel<<<BTOT, 256>>>(ca1_w, ca2_w, out);
    gemm_kernel<PLV, 2, 1><<<dim3(MTOT/128, 1), 256>>>(nullptr, fc_b, out, CINV);
}

// round 3
// speedup vs baseline: 2.2805x; 1.0008x over previous
#include <cuda_runtime.h>
#include <math.h>

#define BTOT 4
#define CINV 128
#define HHV 64
#define WWV 64
#define PLV 256
#define ATTV 64
#define RRV 16
#define STEPSV 6
#define EPSV 1e-6f
#define MTOT (BTOT*HHV*WWV)   /* 16384 */
#define HWV (HHV*WWV)         /* 4096 */

// ---------------- scratch (device globals; no runtime allocation) ----------------
__device__ float g_y[MTOT*PLV];      // conv1 output, NHWC [pix][p]
__device__ float g_xm[MTOT*PLV];     // depthwise+bias output, NHWC
__device__ float g_xl[MTOT*PLV];     // relu(lower) output
__device__ float g_feat[MTOT*PLV];   // relu(xm+xr)
__device__ float g_w1t[CINV*PLV];    // conv1_w transposed [c][p]
__device__ float g_lwt[PLV*PLV];     // lower_w transposed [k][n]
__device__ float g_fwt[PLV*CINV];    // fc_w transposed [p][o]
__device__ float g_att[BTOT*PLV];
__device__ float g_pool_sum[BTOT*PLV];
__device__ int   g_pool_max[BTOT*PLV];

// ---------------- init: zero pools + transpose weights ----------------
__global__ void init_kernel(const float* __restrict__ w1,
                            const float* __restrict__ lw,
                            const float* __restrict__ fw)
{
    int i = blockIdx.x * 256 + threadIdx.x;     // grid 256 -> 65536 threads
    if (i < BTOT*PLV) { g_pool_sum[i] = 0.f; g_pool_max[i] = 0; }
    if (i < CINV*PLV) { int c = i / PLV, p = i % PLV; g_w1t[i] = w1[p*CINV + c]; }
    if (i < PLV*PLV)  { int k = i / PLV, n = i % PLV; g_lwt[i] = lw[n*PLV + k]; }
    if (i < PLV*CINV) { int p = i / CINV, o = i % CINV; g_fwt[i] = fw[o*PLV + p]; }
}

// ---------------- tiled SIMT GEMM (128x128 tile, 8x8 per thread, ktile 16) --------
// MODE 0: y = x @ w1t            (A = x, k-major layout; C = g_y)
// MODE 1: xl = relu(xm@lwt + b)  (A = g_xm row-major; C = g_xl)
// MODE 2: out = (feat*att)@fwt+b (A = g_feat row-major scaled by g_att; C = param, NCHW)
template<int KDIM, int MODE, int ALAYOUT>
__global__ __launch_bounds__(256, 2)
void gemm_kernel(const float* __restrict__ Aparam, const float* __restrict__ bias,
                 float* __restrict__ Cparam, int Ncols)
{
    const float* A  = (MODE==0) ? Aparam : (MODE==1) ? g_xm : g_feat;
    const float* Bt = (MODE==0) ? g_w1t  : (MODE==1) ? g_lwt : g_fwt;
    float*       C  = (MODE==0) ? g_y    : (MODE==1) ? g_xl  : Cparam;

    __shared__ float As[16][132];
    __shared__ float Bs[16][132];
    const int m0 = blockIdx.x * 128;
    const int n0 = blockIdx.y * 128;
    const int t  = threadIdx.x;
    const int tx = t & 15;
    const int ty = t >> 4;
    const int batch = m0 >> 12;

    float acc[8][8];
#pragma unroll
    for (int i = 0; i < 8; i++)
#pragma unroll
        for (int j = 0; j < 8; j++) acc[i][j] = 0.f;

    for (int k0 = 0; k0 < KDIM; k0 += 16) {
        if (ALAYOUT == 0) {
#pragma unroll
            for (int r = 0; r < 2; r++) {
                const int idx = t + 256*r;
                const int ka = idx >> 5, mv = (idx & 31) << 2;
                *(float4*)&As[ka][mv] =
                    *(const float4*)(A + (size_t)batch*KDIM*HWV
                                     + (size_t)(k0+ka)*HWV + (m0 & (HWV-1)) + mv);
            }
        } else {
#pragma unroll
            for (int r = 0; r < 2; r++) {
                const int idx = t + 256*r;
                const int ma = idx >> 2, kv = (idx & 3) << 2;
                float4 v = *(const float4*)(A + (size_t)(m0+ma)*KDIM + k0 + kv);
                if (MODE == 2) {
                    const float4 sc = *(const float4*)(g_att + batch*PLV + k0 + kv);
                    v.x *= sc.x; v.y *= sc.y; v.z *= sc.z; v.w *= sc.w;
                }
                As[kv+0][ma] = v.x; As[kv+1][ma] = v.y;
                As[kv+2][ma] = v.z; As[kv+3][ma] = v.w;
            }
        }
#pragma unroll
        for (int r = 0; r < 2; r++) {
            const int idx = t + 256*r;
            const int kb = idx >> 5, nv = (idx & 31) << 2;
            *(float4*)&Bs[kb][nv] = *(const float4*)(Bt + (size_t)(k0+kb)*Ncols + n0 + nv);
        }
        __syncthreads();
#pragma unroll
        for (int k = 0; k < 16; k++) {
            float4 a0 = *(float4*)&As[k][ty<<2];
            float4 a1 = *(float4*)&As[k][64 + (ty<<2)];
            float4 b0 = *(float4*)&Bs[k][tx<<2];
            float4 b1 = *(float4*)&Bs[k][64 + (tx<<2)];
            float am[8] = {a0.x,a0.y,a0.z,a0.w,a1.x,a1.y,a1.z,a1.w};
            float bn[8] = {b0.x,b0.y,b0.z,b0.w,b1.x,b1.y,b1.z,b1.w};
#pragma unroll
            for (int i = 0; i < 8; i++)
#pragma unroll
                for (int j = 0; j < 8; j++)
                    acc[i][j] = fmaf(am[i], bn[j], acc[i][j]);
        }
        __syncthreads();
    }

#pragma unroll
    for (int i = 0; i < 8; i++) {
        const int mr = (i < 4) ? ((ty<<2) + i) : (64 + (ty<<2) + i - 4);
        const int m  = m0 + mr;
#pragma unroll
        for (int jj = 0; jj < 2; jj++) {
            float4 v;
            v.x = acc[i][jj*4+0]; v.y = acc[i][jj*4+1];
            v.z = acc[i][jj*4+2]; v.w = acc[i][jj*4+3];
            const int n = n0 + (tx<<2) + jj*64;
            if (MODE == 0) {
                *(float4*)&C[(size_t)m*Ncols + n] = v;
            } else if (MODE == 1) {
                const float4 bb = *(const float4*)(bias + n);
                v.x = fmaxf(v.x + bb.x, 0.f);
                v.y = fmaxf(v.y + bb.y, 0.f);
                v.z = fmaxf(v.z + bb.z, 0.f);
                v.w = fmaxf(v.w + bb.w, 0.f);
                *(float4*)&C[(size_t)m*Ncols + n] = v;
            } else {
                const int pix = m & (HWV-1);
#pragma unroll
                for (int qq = 0; qq < 4; qq++) {
                    C[(size_t)(batch*CINV + n + qq)*HWV + pix] = acc[i][jj*4+qq] + bias[n+qq];
                }
            }
        }
    }
}

// ---------------- depthwise 3x3 + bias, NHWC ----------------
__global__ __launch_bounds__(256)
void dw_kernel(const float* __restrict__ w3, const float* __restrict__ b3)
{
    const int p = threadIdx.x;
    float wv[9];
#pragma unroll
    for (int j = 0; j < 9; j++) wv[j] = w3[p*9 + j];
    const float bb = b3[p];
    const int base = blockIdx.x * 4;
    for (int q = 0; q < 4; q++) {
        const int pix = base + q;
        const int b = pix >> 12, hw = pix & 4095, h = hw >> 6, w = hw & 63;
        float acc = bb;
#pragma unroll
        for (int ky = 0; ky < 3; ky++) {
            const int hh = h + ky - 1;
            if (hh < 0 || hh >= HHV) continue;
#pragma unroll
            for (int kx = 0; kx < 3; kx++) {
                const int ww = w + kx - 1;
                if (ww < 0 || ww >= WWV) continue;
                acc = fmaf(g_y[(size_t)((b<<12) + (hh<<6) + ww)*PLV + p], wv[ky*3+kx], acc);
            }
        }
        g_xm[(size_t)pix*PLV + p] = acc;
    }
}

// ---------------- FAST EM: scalar path for r-uniform bases (one warp / pixel) -----
// If all 16 initial b_r are bit-equal (true for uniform[0,1) init: v/max(v,1e-12)
// == 1.0 exactly), coef stays uniform across r by induction (all per-r arithmetic
// is identical; sums of 16 equal fp values are exact *16). The EM collapses to a
// scalar recurrence. Non-uniform warps are skipped here; em_general handles them.
__global__ __launch_bounds__(512)
void em_fast(const float* __restrict__ binit)
{
    __shared__ float bsum[PLV];
    __shared__ int   bmx[PLV];
    const int t = threadIdx.x;
    if (t < PLV) { bsum[t] = 0.f; bmx[t] = 0; }
    __syncthreads();

    const int w = t >> 5, lane = t & 31;
    const int m = blockIdx.x * 16 + w;

    float bv = 1.f;
    if (lane < RRV) {
        const float v = binit[m*RRV + lane];
        bv = v / fmaxf(fabsf(v), 1e-12f);
    }
    const float b0 = __shfl_sync(0xffffffffu, bv, 0);
    const bool uni = __all_sync(0xffffffffu, (lane >= RRV) || (bv == b0));

    if (uni) {
        float b = b0;
        float x[8], cf[8];
        {
            const float4 v0 = *(const float4*)(g_xl + (size_t)m*PLV + lane*8);
            const float4 v1 = *(const float4*)(g_xl + (size_t)m*PLV + lane*8 + 4);
            x[0]=v0.x; x[1]=v0.y; x[2]=v0.z; x[3]=v0.w;
            x[4]=v1.x; x[5]=v1.y; x[6]=v1.z; x[7]=v1.w;
        }
#pragma unroll
        for (int j = 0; j < 8; j++) cf[j] = 0.0625f;   // softmax of equal logits

#pragma unroll
        for (int step = 0; step < STEPSV; step++) {
            // coef update: den = 16*cf*b*b + eps ; cf *= (x*b)/den
            float ps = 0.f, qs = 0.f;
#pragma unroll
            for (int j = 0; j < 8; j++) {
                const float tb  = cf[j] * b;
                const float den = fmaf(16.f*tb, b, EPSV);
                const float num = x[j] * b;
                cf[j] = cf[j] * num * __fdividef(1.f, den);
                ps = fmaf(x[j],  cf[j], ps);     // p = sum x*cf
                qs = fmaf(cf[j], cf[j], qs);     // q' = sum cf^2  (q = 16*b*q')
            }
#pragma unroll
            for (int off = 16; off > 0; off >>= 1) {
                ps += __shfl_xor_sync(0xffffffffu, ps, off);
                qs += __shfl_xor_sync(0xffffffffu, qs, off);
            }
            const float den = fmaf(16.f*b, qs, EPSV);
            b = b * ps * __fdividef(1.f, den);
        }
        // final coef update
#pragma unroll
        for (int j = 0; j < 8; j++) {
            const float tb  = cf[j] * b;
            const float den = fmaf(16.f*tb, b, EPSV);
            const float num = x[j] * b;
            cf[j] = cf[j] * num * __fdividef(1.f, den);
        }
        // xr = 16*b*cf ; feat = relu(xm + xr) ; pooling
        const float4 m0v = *(const float4*)(g_xm + (size_t)m*PLV + lane*8);
        const float4 m1v = *(const float4*)(g_xm + (size_t)m*PLV + lane*8 + 4);
        const float xm8[8] = {m0v.x,m0v.y,m0v.z,m0v.w,m1v.x,m1v.y,m1v.z,m1v.w};
        float f[8];
#pragma unroll
        for (int j = 0; j < 8; j++) {
            f[j] = fmaxf(fmaf(16.f*b, cf[j], xm8[j]), 0.f);
            const int n = lane*8 + j;
            atomicAdd(&bsum[n], f[j]);
            atomicMax(&bmx[n], __float_as_int(f[j]));
        }
        float4 o0 = make_float4(f[0],f[1],f[2],f[3]);
        float4 o1 = make_float4(f[4],f[5],f[6],f[7]);
        *(float4*)(g_feat + (size_t)m*PLV + lane*8)     = o0;
        *(float4*)(g_feat + (size_t)m*PLV + lane*8 + 4) = o1;
    }
    __syncthreads();
    if (t < PLV) {
        const int bb = (blockIdx.x * 16) >> 12;
        atomicAdd(&g_pool_sum[bb*PLV + t], bsum[t]);
        atomicMax(&g_pool_max[bb*PLV + t], bmx[t]);
    }
}

// ---------------- GENERAL EM (fallback for non-uniform warps) ----------------
__global__ __launch_bounds__(256, 1)
void em_general(const float* __restrict__ binit)
{
    __shared__ float bsum[PLV];
    __shared__ int   bmx[PLV];
    const int t = threadIdx.x;
    bsum[t] = 0.f; bmx[t] = 0;
    __syncthreads();

    const int w = t >> 5, lane = t & 31;
    const int m = blockIdx.x * 8 + w;

    float b[RRV];
#pragma unroll
    for (int r = 0; r < RRV; r++) {
        const float v = binit[m*RRV + r];
        b[r] = v / fmaxf(fabsf(v), 1e-12f);
    }
    bool uni = true;
#pragma unroll
    for (int r = 1; r < RRV; r++) uni &= (b[r] == b[0]);

    bool did = false;
    if (!uni) {
        did = true;
        float x[8];
#pragma unroll
        for (int j = 0; j < 8; j++) x[j] = g_xl[(size_t)m*PLV + lane + 32*j];

        float cf[8][RRV];
#pragma unroll
        for (int j = 0; j < 8; j++) {
            const float xn = x[j];
            float tv[RRV]; float mx = -3.4e38f;
#pragma unroll
            for (int r = 0; r < RRV; r++) { tv[r] = xn * b[r]; mx = fmaxf(mx, tv[r]); }
            float s = 0.f;
#pragma unroll
            for (int r = 0; r < RRV; r++) { const float e = __expf(tv[r]-mx); cf[j][r]=e; s+=e; }
            const float inv = __fdividef(1.f, s);
#pragma unroll
            for (int r = 0; r < RRV; r++) cf[j][r] *= inv;
        }
        for (int step = 0; step < STEPSV; step++) {
#pragma unroll
            for (int j = 0; j < 8; j++) {
                float s = 0.f;
#pragma unroll
                for (int r = 0; r < RRV; r++) s = fmaf(cf[j][r], b[r], s);
                const float xn = x[j];
#pragma unroll
                for (int r = 0; r < RRV; r++) {
                    const float num = xn * b[r];
                    const float den = fmaf(s, b[r], EPSV);
                    cf[j][r] = cf[j][r] * num * __fdividef(1.f, den);
                }
            }
            float p[RRV], q[RRV];
#pragma unroll
            for (int r = 0; r < RRV; r++) { p[r]=0.f; q[r]=0.f; }
#pragma unroll
            for (int j = 0; j < 8; j++) {
                float sp = 0.f;
#pragma unroll
                for (int r = 0; r < RRV; r++) sp = fmaf(cf[j][r], b[r], sp);
                const float xn = x[j];
#pragma unroll
                for (int r = 0; r < RRV; r++) {
                    p[r] = fmaf(xn, cf[j][r], p[r]);
                    q[r] = fmaf(sp, cf[j][r], q[r]);
                }
            }
#pragma unroll
            for (int off = 16; off > 0; off >>= 1) {
#pragma unroll
                for (int r = 0; r < RRV; r++) {
                    p[r] += __shfl_xor_sync(0xffffffffu, p[r], off);
                    q[r] += __shfl_xor_sync(0xffffffffu, q[r], off);
                }
            }
#pragma unroll
            for (int r = 0; r < RRV; r++)
                b[r] = b[r] * p[r] * __fdividef(1.f, q[r] + EPSV);
        }
#pragma unroll
        for (int j = 0; j < 8; j++) {
            float s = 0.f;
#pragma unroll
            for (int r = 0; r < RRV; r++) s = fmaf(cf[j][r], b[r], s);
            const float xn = x[j];
#pragma unroll
            for (int r = 0; r < RRV; r++) {
                const float num = xn * b[r];
                const float den = fmaf(s, b[r], EPSV);
                cf[j][r] = cf[j][r] * num * __fdividef(1.f, den);
            }
        }
#pragma unroll
        for (int j = 0; j < 8; j++) {
            float xr = 0.f;
#pragma unroll
            for (int r = 0; r < RRV; r++) xr = fmaf(b[r], cf[j][r], xr);
            const int n = lane + 32*j;
            const float f = fmaxf(g_xm[(size_t)m*PLV + n] + xr, 0.f);
            g_feat[(size_t)m*PLV + n] = f;
            atomicAdd(&bsum[n], f);
            atomicMax(&bmx[n], __float_as_int(f));
        }
    }
    __syncthreads();
    if (__syncthreads_or(did)) {
        const int bb = (blockIdx.x * 8) >> 12;
        atomicAdd(&g_pool_sum[bb*PLV + t], bsum[t]);
        atomicMax(&g_pool_max[bb*PLV + t], bmx[t]);
    }
}

// ---------------- channel attention ----------------
__global__ __launch_bounds__(256)
void ca_kernel(const float* __restrict__ ca1, const float* __restrict__ ca2,
               float* __restrict__ out)
{
    const int b = blockIdx.x;
    const int t = threadIdx.x;
    __shared__ float sAvg[PLV], sMx[PLV], h1[ATTV];
    sAvg[t] = g_pool_sum[b*PLV + t] * (1.0f/(float)HWV);
    sMx[t]  = __int_as_float(g_pool_max[b*PLV + t]);
    __syncthreads();
    if (t < ATTV) {
        float a1 = 0.f, a2 = 0.f;
        for (int p = 0; p < PLV; p++) {
            const float wv = ca1[t*PLV + p];
            a1 = fmaf(wv, sAvg[p], a1);
            a2 = fmaf(wv, sMx[p],  a2);
        }
        h1[t] = fmaxf(a1, 0.f) + fmaxf(a2, 0.f);   // second layer is linear -> sum first
    }
    __syncthreads();
    float v = 0.f;
    for (int a = 0; a < ATTV; a++) v = fmaf(h1[a], ca2[t*ATTV + a], v);
    const float att = __fdividef(1.f, 1.f + __expf(-v));
    g_att[b*PLV + t] = att;
    out[(size_t)BTOT*CINV*HWV + b*PLV + t] = att;   // att output after `out` block
}

// ---------------- launch ----------------
extern "C" void kernel_launch(void* const* d_in, const int* in_sizes, int n_in,
                              void* d_out, int out_size)
{
    const float* x       = (const float*)d_in[0];
    const float* conv1_w = (const float*)d_in[1];
    const float* conv3_w = (const float*)d_in[2];
    const float* conv3_b = (const float*)d_in[3];
    const float* lower_w = (const float*)d_in[4];
    const float* lower_b = (const float*)d_in[5];
    const float* ca1_w   = (const float*)d_in[6];
    const float* ca2_w   = (const float*)d_in[7];
    const float* fc_w    = (const float*)d_in[8];
    const float* fc_b    = (const float*)d_in[9];
    const float* bases   = (const float*)d_in[10];
    float* out = (float*)d_out;

    init_kernel<<<256, 256>>>(conv1_w, lower_w, fc_w);
    gemm_kernel<CINV, 0, 0><<<dim3(MTOT/128, PLV/128), 256>>>(x, nullptr, nullptr, PLV);
    dw_kernel<<<MTOT/4, 256>>>(conv3_w, conv3_b);
    gemm_kernel<PLV, 1, 1><<<dim3(MTOT/128, PLV/128), 256>>>(nullptr, lower_b, nullptr, PLV);
    em_fast<<<MTOT/16, 512>>>(bases);
    em_general<<<MTOT/8, 256>>>(bases);
    ca_kernel<<<BTOT, 256>>>(ca1_w, ca2_w, out);
    gemm_kernel<PLV, 2, 1><<<dim3(MTOT/128, 1), 256>>>(nullptr, fc_b, out, CINV);
}